// round 1
// baseline (speedup 1.0000x reference)
#include <cuda_runtime.h>
#include <math.h>

#define BB 16
#define NN 8192
#define CC 64
#define KK 128
#define K2 256
#define KW 320
#define RR 4
#define NL 4
#define NCHUNK 16
#define INVN (1.0f/8192.0f)

// Z layout per batch: rows 0..127 = cos bases*mask, 128..255 = sin bases*mask,
// rows 256..319 = current h (updated in place each layer).
__device__ float g_Z[(size_t)BB*KW*NN];          // ~168 MB
__device__ float g_X2p[(size_t)BB*NCHUNK*CC*K2]; // forward split-K partials
__device__ float g_X2[BB*CC*K2];
__device__ float g_W[BB*CC*K2];                  // [2*f_c | -2*f_s]
__device__ float g_x0[BB*CC];
__device__ float g_f0[BB*CC];
__device__ float g_wsz[BB*NN];
__device__ float g_mask[BB*NN];

// ---------------------------------------------------------------------------
// Precompute: h0 = fc0(x), bases via complex recurrence (2 sincosf per point)
// ---------------------------------------------------------------------------
__global__ void __launch_bounds__(256) k_pre(const float* __restrict__ x,
                                             const float* __restrict__ fc0w,
                                             const float* __restrict__ fc0b) {
    int idx = blockIdx.x * blockDim.x + threadIdx.x;   // b*NN + n
    int b = idx >> 13, n = idx & (NN - 1);
    const float* xp = x + (size_t)idx * 7;
    float f0 = xp[0], f1 = xp[1], f2 = xp[2];
    float gx = xp[3], gy = xp[4], w = xp[5], m = xp[6];
    g_wsz[idx]  = w * (float)NN;
    g_mask[idx] = m;

    float* Zb = g_Z + (size_t)b * KW * NN;
    #pragma unroll
    for (int c = 0; c < CC; c++) {
        float h = fc0b[c] + f0 * fc0w[c] + f1 * fc0w[CC + c] + f2 * fc0w[2 * CC + c];
        Zb[(size_t)(K2 + c) * NN + n] = h;
    }

    const float TWO_PI = 6.283185307179586f;
    float c1x, s1x, c1y, s1y;
    sincosf(TWO_PI * gx, &s1x, &c1x);
    sincosf(TWO_PI * gy, &s1y, &c1y);
    float cx[16], sx[16], cy[8], sy[8];
    cx[0] = 1.f; sx[0] = 0.f;
    #pragma unroll
    for (int j = 1; j < 16; j++) {
        cx[j] = cx[j-1]*c1x - sx[j-1]*s1x;
        sx[j] = sx[j-1]*c1x + cx[j-1]*s1x;
    }
    cy[0] = 1.f; sy[0] = 0.f;
    #pragma unroll
    for (int j = 1; j < 8; j++) {
        cy[j] = cy[j-1]*c1y - sy[j-1]*s1y;
        sy[j] = sy[j-1]*c1y + cy[j-1]*s1y;
    }
    #pragma unroll 8
    for (int k = 0; k < KK; k++) {
        int kxi = k >> 3, kyi = k & 7;
        float ck = cx[kxi]*cy[kyi] - sx[kxi]*sy[kyi];
        float sk = sx[kxi]*cy[kyi] + cx[kxi]*sy[kyi];
        Zb[(size_t)k * NN + n]        = ck * m;
        Zb[(size_t)(KK + k) * NN + n] = sk * m;
    }
}

// ---------------------------------------------------------------------------
// Forward transform: partial X2[b][c][k2] = sum_n h[c,n]*wsz[n]*base[k2,n]
// block tile 64c x 128k2, split-K over 16 chunks. Per-thread frag 4x8.
// ---------------------------------------------------------------------------
__global__ void __launch_bounds__(256) k_fwd() {
    int b = blockIdx.z, chunk = blockIdx.y, kt = blockIdx.x;
    const float* Zb = g_Z + (size_t)b * KW * NN;
    const float* wszb = g_wsz + b * NN;
    __shared__ float Hs[CC][33];
    __shared__ float Bs[32][132];
    int t = threadIdx.x;
    int tx = t & 15, ty = t >> 4;
    int tx8 = tx * 8, ty4 = ty * 4;
    float acc[4][8];
    #pragma unroll
    for (int u = 0; u < 4; u++)
        #pragma unroll
        for (int v = 0; v < 8; v++) acc[u][v] = 0.f;

    int n0 = chunk * (NN / NCHUNK);
    int nend = n0 + NN / NCHUNK;
    for (; n0 < nend; n0 += 32) {
        #pragma unroll
        for (int i = 0; i < 8; i++) {
            int idx = t + i * 256; int c = idx >> 5, nn = idx & 31;
            Hs[c][nn] = Zb[(size_t)(K2 + c) * NN + n0 + nn] * wszb[n0 + nn];
        }
        #pragma unroll
        for (int i = 0; i < 16; i++) {
            int idx = t + i * 256; int kk = idx >> 5, nn = idx & 31;
            Bs[nn][kk] = Zb[(size_t)(kt * 128 + kk) * NN + n0 + nn];
        }
        __syncthreads();
        #pragma unroll
        for (int nn = 0; nn < 32; nn++) {
            float a[4];
            #pragma unroll
            for (int u = 0; u < 4; u++) a[u] = Hs[ty4 + u][nn];
            float4 p = *(const float4*)&Bs[nn][tx8];
            float4 q = *(const float4*)&Bs[nn][tx8 + 4];
            float bv[8] = {p.x, p.y, p.z, p.w, q.x, q.y, q.z, q.w};
            #pragma unroll
            for (int u = 0; u < 4; u++)
                #pragma unroll
                for (int v = 0; v < 8; v++) acc[u][v] += a[u] * bv[v];
        }
        __syncthreads();
    }
    float* P = g_X2p + (size_t)(b * NCHUNK + chunk) * CC * K2;
    #pragma unroll
    for (int u = 0; u < 4; u++)
        #pragma unroll
        for (int v = 0; v < 8; v++)
            P[(ty4 + u) * K2 + kt * 128 + tx8 + v] = acc[u][v];
}

__global__ void k_reduce() {
    int idx = blockIdx.x * 256 + threadIdx.x;    // < BB*CC*K2
    int b = idx / (CC * K2);
    int rem = idx - b * (CC * K2);
    float s = 0.f;
    #pragma unroll
    for (int ch = 0; ch < NCHUNK; ch++)
        s += g_X2p[(size_t)(b * NCHUNK + ch) * CC * K2 + rem];
    g_X2[idx] = s;
}

// x_0[b][c] = sum_n h[c,n]*mask[n]*wsz[n]
__global__ void k_x0() {
    int c = blockIdx.x, b = blockIdx.y;
    const float* h  = g_Z + (size_t)b * KW * NN + (size_t)(K2 + c) * NN;
    const float* mk = g_mask + b * NN;
    const float* ws = g_wsz + b * NN;
    float s = 0.f;
    for (int n = threadIdx.x; n < NN; n += 256)
        s += h[n] * mk[n] * ws[n];
    __shared__ float red[8];
    for (int o = 16; o > 0; o >>= 1) s += __shfl_down_sync(0xffffffffu, s, o);
    if ((threadIdx.x & 31) == 0) red[threadIdx.x >> 5] = s;
    __syncthreads();
    if (threadIdx.x == 0) {
        float tot = 0.f;
        #pragma unroll
        for (int i = 0; i < 8; i++) tot += red[i];
        g_x0[b * CC + c] = tot;
    }
}

__global__ void k_f0(const float* __restrict__ w01, const float* __restrict__ w02, int l) {
    int b = blockIdx.x, o = threadIdx.x;
    __shared__ float xs[CC];
    xs[o] = g_x0[b * CC + o];
    __syncthreads();
    float f = 0.f;
    #pragma unroll
    for (int r = 0; r < RR; r++) {
        float u = 0.f;
        #pragma unroll 8
        for (int i = 0; i < CC; i++) u += xs[i] * w01[(l * CC + i) * RR + r];
        f += u * w02[(l * RR + r) * CC + o];
    }
    g_f0[b * CC + o] = f * INVN;
}

// Low-rank mixing per (b,k): builds W = [2*f_c | -2*f_s] (incl. 1/N scale)
__global__ void k_lowrank(const float* __restrict__ wc1, const float* __restrict__ wc2,
                          const float* __restrict__ ws1, const float* __restrict__ ws2, int l) {
    int k = blockIdx.x, b = blockIdx.y, o = threadIdx.x;
    __shared__ float xc[CC], xsm[CC];
    __shared__ float u[4][RR];
    xc[o]  =  g_X2[(b * CC + o) * K2 + k];
    xsm[o] = -g_X2[(b * CC + o) * K2 + KK + k];
    __syncthreads();
    if (o < 16) {
        int which = o >> 2, r = o & 3;
        const float* src = (which >> 1) ? xsm : xc;
        const float* W1 = ((which & 1) ? ws1 : wc1) + (size_t)l * CC * RR * KK;
        float s = 0.f;
        #pragma unroll 8
        for (int i = 0; i < CC; i++) s += src[i] * W1[(i * RR + r) * KK + k];
        u[which][r] = s;
    }
    __syncthreads();
    float fc = 0.f, fs = 0.f;
    #pragma unroll
    for (int r = 0; r < RR; r++) {
        float c2v = wc2[((l * RR + r) * CC + o) * KK + k];
        float s2v = ws2[((l * RR + r) * CC + o) * KK + k];
        fc += u[0][r] * c2v - u[3][r] * s2v;   // (xc·c1)·c2 - (xs·s1)·s2
        fs += u[2][r] * c2v + u[1][r] * s2v;   // (xs·c1)·c2 + (xc·s1)·s2
    }
    g_W[(b * CC + o) * K2 + k]      =  2.f * INVN * fc;
    g_W[(b * CC + o) * K2 + KK + k] = -2.f * INVN * fs;
}

// ---------------------------------------------------------------------------
// Inverse transform + conv + bias (+gelu), all as one GEMM:
//   h_new[c,n] = sum_{k2<320} W[c,k2]*Z[k2,n] + f0[c]*mask[n] + bconv[c]
// with W rows 256..319 = wconv^T and Z rows 256..319 = current h.
// In-place update of h (each block owns its n columns).
// ---------------------------------------------------------------------------
__global__ void __launch_bounds__(256) k_inv(const float* __restrict__ wconv,
                                             const float* __restrict__ bconv,
                                             int l, int do_gelu) {
    int nt = blockIdx.x, b = blockIdx.y;
    int n0 = nt * 128;
    float* Zb = g_Z + (size_t)b * KW * NN;
    const float* Wb = g_W + (size_t)b * CC * K2;
    const float* wcv = wconv + l * CC * CC;
    __shared__ float Ws[CC][33];
    __shared__ float Zs[32][132];
    int t = threadIdx.x;
    int tx = t & 15, ty = t >> 4;
    int tx8 = tx * 8, ty4 = ty * 4;
    float acc[4][8];
    #pragma unroll
    for (int u = 0; u < 4; u++)
        #pragma unroll
        for (int v = 0; v < 8; v++) acc[u][v] = 0.f;

    for (int k0 = 0; k0 < KW; k0 += 32) {
        #pragma unroll
        for (int i = 0; i < 8; i++) {
            int idx = t + i * 256; int c = idx >> 5, kk = idx & 31;
            int k2 = k0 + kk;
            Ws[c][kk] = (k2 < K2) ? Wb[c * K2 + k2] : wcv[(k2 - K2) * CC + c];
        }
        #pragma unroll
        for (int i = 0; i < 16; i++) {
            int idx = t + i * 256; int kk = idx >> 7, nl = idx & 127;
            Zs[kk][nl] = Zb[(size_t)(k0 + kk) * NN + n0 + nl];
        }
        __syncthreads();
        #pragma unroll
        for (int kk = 0; kk < 32; kk++) {
            float a[4];
            #pragma unroll
            for (int u = 0; u < 4; u++) a[u] = Ws[ty4 + u][kk];
            float4 p = *(const float4*)&Zs[kk][tx8];
            float4 q = *(const float4*)&Zs[kk][tx8 + 4];
            float bv[8] = {p.x, p.y, p.z, p.w, q.x, q.y, q.z, q.w};
            #pragma unroll
            for (int u = 0; u < 4; u++)
                #pragma unroll
                for (int v = 0; v < 8; v++) acc[u][v] += a[u] * bv[v];
        }
        __syncthreads();
    }
    const float* mk = g_mask + b * NN;
    #pragma unroll
    for (int u = 0; u < 4; u++) {
        int c = ty4 + u;
        float f0v = g_f0[b * CC + c];
        float bcv = bconv[l * CC + c];
        float ov[8];
        #pragma unroll
        for (int v = 0; v < 8; v++) {
            int n = n0 + tx8 + v;
            float val = acc[u][v] + f0v * mk[n] + bcv;
            if (do_gelu) val = val * normcdff(val);  // exact gelu
            ov[v] = val;
        }
        float* dst = &Zb[(size_t)(K2 + c) * NN + n0 + tx8];
        *(float4*)dst       = make_float4(ov[0], ov[1], ov[2], ov[3]);
        *(float4*)(dst + 4) = make_float4(ov[4], ov[5], ov[6], ov[7]);
    }
}

// Final MLP: out = fc2(gelu(fc1(h))); one thread per point, h in registers.
__global__ void __launch_bounds__(256) k_mlp(const float* __restrict__ w1,
                                             const float* __restrict__ b1,
                                             const float* __restrict__ w2,
                                             const float* __restrict__ b2,
                                             float* __restrict__ out) {
    __shared__ float Wsm[CC * 128];
    __shared__ float b1s[128], w2s[128];
    int t = threadIdx.x;
    for (int i = t; i < CC * 128; i += 256) Wsm[i] = w1[i];
    if (t < 128) { b1s[t] = b1[t]; w2s[t] = w2[t]; }
    __syncthreads();
    int b = blockIdx.y;
    int n = blockIdx.x * 256 + t;
    const float* Zb = g_Z + (size_t)b * KW * NN;
    float h[CC];
    #pragma unroll
    for (int c = 0; c < CC; c++) h[c] = Zb[(size_t)(K2 + c) * NN + n];
    float acc = b2[0];
    #pragma unroll 2
    for (int j = 0; j < 128; j++) {
        float a = b1s[j];
        #pragma unroll
        for (int c = 0; c < CC; c++) a += h[c] * Wsm[c * 128 + j];
        acc += (a * normcdff(a)) * w2s[j];
    }
    out[(size_t)b * NN + n] = acc;
}

extern "C" void kernel_launch(void* const* d_in, const int* in_sizes, int n_in,
                              void* d_out, int out_size) {
    const float* x    = (const float*)d_in[0];
    const float* fc0w = (const float*)d_in[1];
    const float* fc0b = (const float*)d_in[2];
    const float* wc1  = (const float*)d_in[3];
    const float* wc2  = (const float*)d_in[4];
    const float* ws1  = (const float*)d_in[5];
    const float* ws2  = (const float*)d_in[6];
    const float* w01  = (const float*)d_in[7];
    const float* w02  = (const float*)d_in[8];
    const float* wconv = (const float*)d_in[9];
    const float* bconv = (const float*)d_in[10];
    const float* fc1w = (const float*)d_in[11];
    const float* fc1b = (const float*)d_in[12];
    const float* fc2w = (const float*)d_in[13];
    const float* fc2b = (const float*)d_in[14];
    float* out = (float*)d_out;

    k_pre<<<BB * NN / 256, 256>>>(x, fc0w, fc0b);
    for (int l = 0; l < NL; l++) {
        k_fwd<<<dim3(2, NCHUNK, BB), 256>>>();
        k_reduce<<<(BB * CC * K2) / 256, 256>>>();
        k_x0<<<dim3(CC, BB), 256>>>();
        k_f0<<<BB, CC>>>(w01, w02, l);
        k_lowrank<<<dim3(KK, BB), CC>>>(wc1, wc2, ws1, ws2, l);
        k_inv<<<dim3(NN / 128, BB), 256>>>(wconv, bconv, l, (l != NL - 1) ? 1 : 0);
    }
    k_mlp<<<dim3(NN / 256, BB), 256>>>(fc1w, fc1b, fc2w, fc2b, out);
}

// round 2
// speedup vs baseline: 1.5247x; 1.5247x over previous
#include <cuda_runtime.h>
#include <math.h>

#define BB 16
#define NN 8192
#define CC 64
#define KK 128
#define K2 256
#define KW 320
#define RR 4
#define NL 4
#define NCHUNK 16
#define INVN (1.0f/8192.0f)

// packed fp32x2 helpers (sm_103a)
#define FMA2(acc, a, b) asm("fma.rn.f32x2 %0, %1, %2, %0;" : "+l"(acc) : "l"(a), "l"(b))
#define PACKF2(out, lo, hi) asm("mov.b64 %0, {%1, %2};" : "=l"(out) : "f"(lo), "f"(hi))
#define UNPACKF2(lo, hi, in) asm("mov.b64 {%0, %1}, %2;" : "=f"(lo), "=f"(hi) : "l"(in))

// Z layout per batch: rows 0..127 = cos bases*mask, 128..255 = sin bases*mask,
// rows 256..319 = current h (updated in place each layer).
__device__ float g_Z[(size_t)BB*KW*NN];          // ~168 MB
__device__ float g_X2p[(size_t)BB*NCHUNK*CC*K2]; // forward split-K partials
__device__ float g_X2[BB*CC*K2];
__device__ float g_W[BB*CC*K2];                  // [2*f_c | -2*f_s]
__device__ float g_x0[BB*CC];
__device__ float g_f0[BB*CC];
__device__ float g_wsz[BB*NN];
__device__ float g_mask[BB*NN];

// ---------------------------------------------------------------------------
// Precompute: h0 = fc0(x), bases via complex recurrence (2 sincosf per point)
// ---------------------------------------------------------------------------
__global__ void __launch_bounds__(256) k_pre(const float* __restrict__ x,
                                             const float* __restrict__ fc0w,
                                             const float* __restrict__ fc0b) {
    int idx = blockIdx.x * blockDim.x + threadIdx.x;   // b*NN + n
    int b = idx >> 13, n = idx & (NN - 1);
    const float* xp = x + (size_t)idx * 7;
    float f0 = xp[0], f1 = xp[1], f2 = xp[2];
    float gx = xp[3], gy = xp[4], w = xp[5], m = xp[6];
    g_wsz[idx]  = w * (float)NN;
    g_mask[idx] = m;

    float* Zb = g_Z + (size_t)b * KW * NN;
    #pragma unroll
    for (int c = 0; c < CC; c++) {
        float h = fc0b[c] + f0 * fc0w[c] + f1 * fc0w[CC + c] + f2 * fc0w[2 * CC + c];
        Zb[(size_t)(K2 + c) * NN + n] = h;
    }

    const float TWO_PI = 6.283185307179586f;
    float c1x, s1x, c1y, s1y;
    sincosf(TWO_PI * gx, &s1x, &c1x);
    sincosf(TWO_PI * gy, &s1y, &c1y);
    float cx[16], sx[16], cy[8], sy[8];
    cx[0] = 1.f; sx[0] = 0.f;
    #pragma unroll
    for (int j = 1; j < 16; j++) {
        cx[j] = cx[j-1]*c1x - sx[j-1]*s1x;
        sx[j] = sx[j-1]*c1x + cx[j-1]*s1x;
    }
    cy[0] = 1.f; sy[0] = 0.f;
    #pragma unroll
    for (int j = 1; j < 8; j++) {
        cy[j] = cy[j-1]*c1y - sy[j-1]*s1y;
        sy[j] = sy[j-1]*c1y + cy[j-1]*s1y;
    }
    #pragma unroll 8
    for (int k = 0; k < KK; k++) {
        int kxi = k >> 3, kyi = k & 7;
        float ck = cx[kxi]*cy[kyi] - sx[kxi]*sy[kyi];
        float sk = sx[kxi]*cy[kyi] + cx[kxi]*sy[kyi];
        Zb[(size_t)k * NN + n]        = ck * m;
        Zb[(size_t)(KK + k) * NN + n] = sk * m;
    }
}

// ---------------------------------------------------------------------------
// Forward transform: partial X2[b][c][k2] = sum_n h[c,n]*wsz[n]*base[k2,n]
// One block = full 64c x 256k2 tile for one (b, n-chunk of 512). FFMA2 8x8 frag.
// ---------------------------------------------------------------------------
__global__ void __launch_bounds__(256, 2) k_fwd() {
    int chunk = blockIdx.x, b = blockIdx.y;
    const float* Zb = g_Z + (size_t)b * KW * NN;
    const float* wszb = g_wsz + b * NN;
    __shared__ float Hs2[16][132];   // [nn][2c] duplicated pairs (h,h)
    __shared__ float Bs[16][260];    // [nn][k2]
    int t = threadIdx.x;
    int ty = t >> 5, tx = t & 31;    // ty: 8 c-groups, tx: 32 k2-groups
    unsigned long long acc[8][4];
    #pragma unroll
    for (int u = 0; u < 8; u++)
        #pragma unroll
        for (int v = 0; v < 4; v++) acc[u][v] = 0ULL;

    int n0 = chunk * (NN / NCHUNK);
    for (int it = 0; it < (NN / NCHUNK) / 16; it++) {
        int nb = n0 + it * 16;
        // Hs2: 64c x 16n, 1 float4/thread, duplicated store
        {
            int c = t >> 2, nj = (t & 3) * 4;
            float4 hv = *(const float4*)&Zb[(size_t)(K2 + c) * NN + nb + nj];
            float4 wv = *(const float4*)&wszb[nb + nj];
            float h0 = hv.x * wv.x, h1 = hv.y * wv.y, h2 = hv.z * wv.z, h3 = hv.w * wv.w;
            Hs2[nj+0][2*c] = h0; Hs2[nj+0][2*c+1] = h0;
            Hs2[nj+1][2*c] = h1; Hs2[nj+1][2*c+1] = h1;
            Hs2[nj+2][2*c] = h2; Hs2[nj+2][2*c+1] = h2;
            Hs2[nj+3][2*c] = h3; Hs2[nj+3][2*c+1] = h3;
        }
        // Bs: 256k2 x 16n, 4 float4/thread, transposed store
        #pragma unroll
        for (int i = 0; i < 4; i++) {
            int idx = t + i * 256;
            int k2 = idx >> 2, nj = (idx & 3) * 4;
            float4 bv = *(const float4*)&Zb[(size_t)k2 * NN + nb + nj];
            Bs[nj+0][k2] = bv.x;
            Bs[nj+1][k2] = bv.y;
            Bs[nj+2][k2] = bv.z;
            Bs[nj+3][k2] = bv.w;
        }
        __syncthreads();
        #pragma unroll
        for (int nn = 0; nn < 16; nn++) {
            ulonglong2 a0 = *(const ulonglong2*)&Hs2[nn][ty*8];
            ulonglong2 a1 = *(const ulonglong2*)&Hs2[nn][ty*8+4];
            ulonglong2 a2 = *(const ulonglong2*)&Hs2[nn][64+ty*8];
            ulonglong2 a3 = *(const ulonglong2*)&Hs2[nn][64+ty*8+4];
            ulonglong2 b0 = *(const ulonglong2*)&Bs[nn][tx*4];
            ulonglong2 b1 = *(const ulonglong2*)&Bs[nn][128+tx*4];
            unsigned long long av[8] = {a0.x, a0.y, a1.x, a1.y, a2.x, a2.y, a3.x, a3.y};
            unsigned long long bv[4] = {b0.x, b0.y, b1.x, b1.y};
            #pragma unroll
            for (int u = 0; u < 8; u++)
                #pragma unroll
                for (int v = 0; v < 4; v++)
                    FMA2(acc[u][v], av[u], bv[v]);
        }
        __syncthreads();
    }
    float* P = g_X2p + (size_t)(b * NCHUNK + chunk) * CC * K2;
    #pragma unroll
    for (int u = 0; u < 8; u++) {
        int cu = (u < 4) ? (ty * 4 + u) : (32 + ty * 4 + u - 4);
        ulonglong2 s0; s0.x = acc[u][0]; s0.y = acc[u][1];
        ulonglong2 s1; s1.x = acc[u][2]; s1.y = acc[u][3];
        *(ulonglong2*)&P[cu * K2 + tx * 4]       = s0;
        *(ulonglong2*)&P[cu * K2 + 128 + tx * 4] = s1;
    }
}

__global__ void k_reduce() {
    int idx = blockIdx.x * 256 + threadIdx.x;    // < BB*CC*K2
    int b = idx / (CC * K2);
    int rem = idx - b * (CC * K2);
    float s = 0.f;
    #pragma unroll
    for (int ch = 0; ch < NCHUNK; ch++)
        s += g_X2p[(size_t)(b * NCHUNK + ch) * CC * K2 + rem];
    g_X2[idx] = s;
}

// x_0[b][c] = sum_n h[c,n]*mask[n]*wsz[n]; 8 channels per block, warp-per-channel
__global__ void __launch_bounds__(256) k_x0() {
    int cg = blockIdx.x, b = blockIdx.y;
    __shared__ float mw[NN];
    int t = threadIdx.x;
    for (int i = t; i < NN; i += 256)
        mw[i] = g_mask[b * NN + i] * g_wsz[b * NN + i];
    __syncthreads();
    int wid = t >> 5, lid = t & 31;
    int c = cg * 8 + wid;
    const float* h = g_Z + (size_t)b * KW * NN + (size_t)(K2 + c) * NN;
    float s = 0.f;
    for (int n = lid; n < NN; n += 32)
        s += h[n] * mw[n];
    #pragma unroll
    for (int o = 16; o > 0; o >>= 1) s += __shfl_down_sync(0xffffffffu, s, o);
    if (lid == 0) g_x0[b * CC + c] = s;
}

__global__ void k_f0(const float* __restrict__ w01, const float* __restrict__ w02, int l) {
    int b = blockIdx.x, o = threadIdx.x;
    __shared__ float xs[CC];
    xs[o] = g_x0[b * CC + o];
    __syncthreads();
    float f = 0.f;
    #pragma unroll
    for (int r = 0; r < RR; r++) {
        float u = 0.f;
        #pragma unroll 8
        for (int i = 0; i < CC; i++) u += xs[i] * w01[(l * CC + i) * RR + r];
        f += u * w02[(l * RR + r) * CC + o];
    }
    g_f0[b * CC + o] = f * INVN;
}

// Low-rank mixing per (b,k): builds W = [2*f_c | -2*f_s] (incl. 1/N scale)
__global__ void k_lowrank(const float* __restrict__ wc1, const float* __restrict__ wc2,
                          const float* __restrict__ ws1, const float* __restrict__ ws2, int l) {
    int k = blockIdx.x, b = blockIdx.y, o = threadIdx.x;
    __shared__ float xc[CC], xsm[CC];
    __shared__ float u[4][RR];
    xc[o]  =  g_X2[(b * CC + o) * K2 + k];
    xsm[o] = -g_X2[(b * CC + o) * K2 + KK + k];
    __syncthreads();
    if (o < 16) {
        int which = o >> 2, r = o & 3;
        const float* src = (which >> 1) ? xsm : xc;
        const float* W1 = ((which & 1) ? ws1 : wc1) + (size_t)l * CC * RR * KK;
        float s = 0.f;
        #pragma unroll 8
        for (int i = 0; i < CC; i++) s += src[i] * W1[(i * RR + r) * KK + k];
        u[which][r] = s;
    }
    __syncthreads();
    float fc = 0.f, fs = 0.f;
    #pragma unroll
    for (int r = 0; r < RR; r++) {
        float c2v = wc2[((l * RR + r) * CC + o) * KK + k];
        float s2v = ws2[((l * RR + r) * CC + o) * KK + k];
        fc += u[0][r] * c2v - u[3][r] * s2v;   // (xc·c1)·c2 - (xs·s1)·s2
        fs += u[2][r] * c2v + u[1][r] * s2v;   // (xs·c1)·c2 + (xc·s1)·s2
    }
    g_W[(b * CC + o) * K2 + k]      =  2.f * INVN * fc;
    g_W[(b * CC + o) * K2 + KK + k] = -2.f * INVN * fs;
}

// ---------------------------------------------------------------------------
// Inverse transform + conv + bias (+gelu), one GEMM:
//   h_new[c,n] = sum_{k2<320} W[c,k2]*Z[k2,n] + f0[c]*mask[n] + bconv[c]
// Block tile: 64c x 256n, K=320 in steps of 16. FFMA2 8x8 frags.
// ---------------------------------------------------------------------------
__global__ void __launch_bounds__(256, 2) k_inv(const float* __restrict__ wconv,
                                                const float* __restrict__ bconv,
                                                int l, int do_gelu) {
    int nt = blockIdx.x, b = blockIdx.y;
    int n0 = nt * 256;
    float* Zb = g_Z + (size_t)b * KW * NN;
    const float* Wb = g_W + (size_t)b * CC * K2;
    const float* wcv = wconv + l * CC * CC;
    __shared__ float Ws2[16][132];   // [kk][2c] duplicated (w,w)
    __shared__ float Zs[16][256];    // [kk][n]
    int t = threadIdx.x;
    int ty = t >> 5, tx = t & 31;
    unsigned long long acc[8][4];
    #pragma unroll
    for (int u = 0; u < 8; u++)
        #pragma unroll
        for (int v = 0; v < 4; v++) acc[u][v] = 0ULL;

    for (int k0 = 0; k0 < KW; k0 += 16) {
        // Ws2: 16kk x 64c duplicated
        {
            int c = t >> 2, kj = (t & 3) * 4;
            float w0, w1, w2, w3;
            if (k0 < K2) {
                float4 wv = *(const float4*)&Wb[c * K2 + k0 + kj];
                w0 = wv.x; w1 = wv.y; w2 = wv.z; w3 = wv.w;
            } else {
                int kq = k0 + kj - K2;
                w0 = wcv[(kq+0) * CC + c];
                w1 = wcv[(kq+1) * CC + c];
                w2 = wcv[(kq+2) * CC + c];
                w3 = wcv[(kq+3) * CC + c];
            }
            Ws2[kj+0][2*c] = w0; Ws2[kj+0][2*c+1] = w0;
            Ws2[kj+1][2*c] = w1; Ws2[kj+1][2*c+1] = w1;
            Ws2[kj+2][2*c] = w2; Ws2[kj+2][2*c+1] = w2;
            Ws2[kj+3][2*c] = w3; Ws2[kj+3][2*c+1] = w3;
        }
        // Zs: 16kk x 256n direct float4
        #pragma unroll
        for (int i = 0; i < 4; i++) {
            int idx = t + i * 256;
            int kk = idx >> 6, nl = (idx & 63) * 4;
            *(float4*)&Zs[kk][nl] = *(const float4*)&Zb[(size_t)(k0 + kk) * NN + n0 + nl];
        }
        __syncthreads();
        #pragma unroll
        for (int kk = 0; kk < 16; kk++) {
            ulonglong2 a0 = *(const ulonglong2*)&Ws2[kk][ty*8];
            ulonglong2 a1 = *(const ulonglong2*)&Ws2[kk][ty*8+4];
            ulonglong2 a2 = *(const ulonglong2*)&Ws2[kk][64+ty*8];
            ulonglong2 a3 = *(const ulonglong2*)&Ws2[kk][64+ty*8+4];
            ulonglong2 b0 = *(const ulonglong2*)&Zs[kk][tx*4];
            ulonglong2 b1 = *(const ulonglong2*)&Zs[kk][128+tx*4];
            unsigned long long av[8] = {a0.x, a0.y, a1.x, a1.y, a2.x, a2.y, a3.x, a3.y};
            unsigned long long bv[4] = {b0.x, b0.y, b1.x, b1.y};
            #pragma unroll
            for (int u = 0; u < 8; u++)
                #pragma unroll
                for (int v = 0; v < 4; v++)
                    FMA2(acc[u][v], av[u], bv[v]);
        }
        __syncthreads();
    }
    const float* mk = g_mask + b * NN;
    #pragma unroll
    for (int u = 0; u < 8; u++) {
        int c = (u < 4) ? (ty * 4 + u) : (32 + ty * 4 + u - 4);
        float f0v = g_f0[b * CC + c];
        float bcv = bconv[l * CC + c];
        float ov[8];
        #pragma unroll
        for (int v = 0; v < 4; v++) {
            float lo, hi;
            UNPACKF2(lo, hi, acc[u][v]);
            ov[2*v] = lo; ov[2*v+1] = hi;
        }
        #pragma unroll
        for (int half = 0; half < 2; half++) {
            int nb = n0 + half * 128 + tx * 4;
            float r[4];
            #pragma unroll
            for (int j = 0; j < 4; j++) {
                float val = ov[half*4 + j] + f0v * mk[nb + j] + bcv;
                if (do_gelu) val = val * normcdff(val);
                r[j] = val;
            }
            *(float4*)&Zb[(size_t)(K2 + c) * NN + nb] = make_float4(r[0], r[1], r[2], r[3]);
        }
    }
}

// Final MLP: out = fc2(gelu(fc1(h))); one thread per point, f32x2 inner product.
__global__ void __launch_bounds__(256) k_mlp(const float* __restrict__ w1,
                                             const float* __restrict__ b1,
                                             const float* __restrict__ w2,
                                             const float* __restrict__ b2,
                                             float* __restrict__ out) {
    __shared__ float Wsm[CC * 128];
    __shared__ float b1s[128], w2s[128];
    int t = threadIdx.x;
    for (int i = t; i < CC * 128; i += 256) Wsm[i] = w1[i];
    if (t < 128) { b1s[t] = b1[t]; w2s[t] = w2[t]; }
    __syncthreads();
    int b = blockIdx.y;
    int n = blockIdx.x * 256 + t;
    const float* Zb = g_Z + (size_t)b * KW * NN;
    float h[CC];
    #pragma unroll
    for (int c = 0; c < CC; c++) h[c] = Zb[(size_t)(K2 + c) * NN + n];
    float acc = b2[0];
    for (int j0 = 0; j0 < 128; j0 += 8) {
        unsigned long long a[4];
        PACKF2(a[0], b1s[j0+0], b1s[j0+1]);
        PACKF2(a[1], b1s[j0+2], b1s[j0+3]);
        PACKF2(a[2], b1s[j0+4], b1s[j0+5]);
        PACKF2(a[3], b1s[j0+6], b1s[j0+7]);
        #pragma unroll
        for (int c = 0; c < CC; c++) {
            unsigned long long hd;
            PACKF2(hd, h[c], h[c]);
            ulonglong2 w0 = *(const ulonglong2*)&Wsm[c * 128 + j0];
            ulonglong2 w1v = *(const ulonglong2*)&Wsm[c * 128 + j0 + 4];
            FMA2(a[0], hd, w0.x);
            FMA2(a[1], hd, w0.y);
            FMA2(a[2], hd, w1v.x);
            FMA2(a[3], hd, w1v.y);
        }
        #pragma unroll
        for (int p = 0; p < 4; p++) {
            float lo, hi;
            UNPACKF2(lo, hi, a[p]);
            acc += (lo * normcdff(lo)) * w2s[j0 + 2*p];
            acc += (hi * normcdff(hi)) * w2s[j0 + 2*p + 1];
        }
    }
    out[(size_t)b * NN + n] = acc;
}

extern "C" void kernel_launch(void* const* d_in, const int* in_sizes, int n_in,
                              void* d_out, int out_size) {
    const float* x    = (const float*)d_in[0];
    const float* fc0w = (const float*)d_in[1];
    const float* fc0b = (const float*)d_in[2];
    const float* wc1  = (const float*)d_in[3];
    const float* wc2  = (const float*)d_in[4];
    const float* ws1  = (const float*)d_in[5];
    const float* ws2  = (const float*)d_in[6];
    const float* w01  = (const float*)d_in[7];
    const float* w02  = (const float*)d_in[8];
    const float* wconv = (const float*)d_in[9];
    const float* bconv = (const float*)d_in[10];
    const float* fc1w = (const float*)d_in[11];
    const float* fc1b = (const float*)d_in[12];
    const float* fc2w = (const float*)d_in[13];
    const float* fc2b = (const float*)d_in[14];
    float* out = (float*)d_out;

    k_pre<<<BB * NN / 256, 256>>>(x, fc0w, fc0b);
    for (int l = 0; l < NL; l++) {
        k_fwd<<<dim3(NCHUNK, BB), 256>>>();
        k_reduce<<<(BB * CC * K2) / 256, 256>>>();
        k_x0<<<dim3(CC / 8, BB), 256>>>();
        k_f0<<<BB, CC>>>(w01, w02, l);
        k_lowrank<<<dim3(KK, BB), CC>>>(wc1, wc2, ws1, ws2, l);
        k_inv<<<dim3(NN / 256, BB), 256>>>(wconv, bconv, l, (l != NL - 1) ? 1 : 0);
    }
    k_mlp<<<dim3(NN / 256, BB), 256>>>(fc1w, fc1b, fc2w, fc2b, out);
}